// round 10
// baseline (speedup 1.0000x reference)
#include <cuda_runtime.h>
#include <cstdint>

#define BATCH  32
#define HW     3136
#define C      256
#define CR     64
#define GPPC   16            // gap pixels per chunk
#define GCH    196           // HW / GPPC
#define MPPC   32            // mul pixels per chunk
#define MCH    98            // HW / MPPC
#define NG     32            // channel groups of 8 floats (C/8)
#define BPG    16            // batches per group (x_group = 51.4 MB << L2)
#define GROUPS 2

// Scratch (allocation-free per harness rules)
__device__ float g_partial[BATCH * GCH * C];
__device__ float g_gate[BATCH * C];

// ---- 256-bit L2 eviction-priority primitives (sm_100+) ---------------------
__device__ __forceinline__ void ld256_evict_last(const float* p, uint32_t* u) {
    asm volatile("ld.global.nc.L2::evict_last.v8.b32 {%0,%1,%2,%3,%4,%5,%6,%7}, [%8];"
                 : "=r"(u[0]), "=r"(u[1]), "=r"(u[2]), "=r"(u[3]),
                   "=r"(u[4]), "=r"(u[5]), "=r"(u[6]), "=r"(u[7])
                 : "l"(p));
}
__device__ __forceinline__ void ld256_evict_first(const float* p, uint32_t* u) {
    asm volatile("ld.global.nc.L2::evict_first.v8.b32 {%0,%1,%2,%3,%4,%5,%6,%7}, [%8];"
                 : "=r"(u[0]), "=r"(u[1]), "=r"(u[2]), "=r"(u[3]),
                   "=r"(u[4]), "=r"(u[5]), "=r"(u[6]), "=r"(u[7])
                 : "l"(p));
}
__device__ __forceinline__ void st256_evict_first(float* p, const uint32_t* u) {
    asm volatile("st.global.L2::evict_first.v8.b32 [%0], {%1,%2,%3,%4,%5,%6,%7,%8};"
                 :: "l"(p),
                    "r"(u[0]), "r"(u[1]), "r"(u[2]), "r"(u[3]),
                    "r"(u[4]), "r"(u[5]), "r"(u[6]), "r"(u[7]));
}

// ---------------------------------------------------------------------------
// gap_kernel: grid = (GCH, BPG) = 3136 blocks, 256 threads, lean (~27 regs).
// c8 = tid&31 (8-ch group), pr = tid>>5 (8 pixel rows). 2 x v8 evict_last
// loads pin the group's x in L2. SMEM reduce -> per-block partial (__stcs so
// partials don't displace pinned x).
// ---------------------------------------------------------------------------
__global__ __launch_bounds__(256) void gap_kernel(const float* __restrict__ x,
                                                  int b0)
{
    const int chunk = blockIdx.x;
    const int b     = b0 + blockIdx.y;
    const int tid   = threadIdx.x;
    const int c8    = tid & (NG - 1);
    const int pr    = tid >> 5;

    const float* xp = x + ((size_t)(b * HW + chunk * GPPC + pr)) * C + c8 * 8;

    uint32_t u0[8], u1[8];
    ld256_evict_last(xp,                 u0);
    ld256_evict_last(xp + (size_t)8 * C, u1);

    __shared__ float red[8 * C];       // 8KB
    float* rp = &red[pr * C + c8 * 8];
#pragma unroll
    for (int k = 0; k < 8; ++k) {
        rp[k] = __uint_as_float(u0[k]) + __uint_as_float(u1[k]);
    }
    __syncthreads();

    float p0 = 0.0f;
#pragma unroll
    for (int g = 0; g < 8; ++g) {
        p0 += red[g * C + tid];
    }
    __stcs(&g_partial[(b * GCH + chunk) * C + tid], p0);
}

// ---------------------------------------------------------------------------
// fc_kernel: BPG blocks x 256 threads. 4-way accumulate over 196 partials,
// then squeeze->relu6->excite->hsigmoid -> gate.
// ---------------------------------------------------------------------------
__global__ __launch_bounds__(256) void fc_kernel(const float* __restrict__ w1,
                                                 const float* __restrict__ w2,
                                                 int b0)
{
    const int b = b0 + blockIdx.x;
    const int t = threadIdx.x;

    __shared__ float s[C];
    __shared__ float h[CR];

    float s0 = 0.f, s1 = 0.f, s2 = 0.f, s3 = 0.f;
#pragma unroll
    for (int k = 0; k < GCH; k += 4) {
        s0 += __ldcg(&g_partial[(b * GCH + k + 0) * C + t]);
        s1 += __ldcg(&g_partial[(b * GCH + k + 1) * C + t]);
        s2 += __ldcg(&g_partial[(b * GCH + k + 2) * C + t]);
        s3 += __ldcg(&g_partial[(b * GCH + k + 3) * C + t]);
    }
    s[t] = ((s0 + s1) + (s2 + s3)) * (1.0f / (float)HW);
    __syncthreads();

    if (t < CR) {
        float acc = 0.0f;
#pragma unroll 8
        for (int c = 0; c < C; ++c) {
            acc += s[c] * w1[c * CR + t];
        }
        h[t] = fminf(fmaxf(acc, 0.0f), 6.0f);
    }
    __syncthreads();

    float acc = 0.0f;
#pragma unroll
    for (int r = 0; r < CR; ++r) {
        acc += h[r] * w2[r * C + t];
    }
    g_gate[b * C + t] = fminf(fmaxf(acc + 3.0f, 0.0f), 6.0f) * (1.0f / 6.0f);
}

// ---------------------------------------------------------------------------
// mul_kernel: grid = (MCH, BPG) = 1568 blocks, 256 threads.
// 4 v8-loads in flight (reads should hit L2 - pinned by gap's evict_last;
// evict_first on read since x is dead after this). 4 v8 evict_first stores:
// the out stream churns its own demoted lines, never pinned x.
// ---------------------------------------------------------------------------
__global__ __launch_bounds__(256) void mul_kernel(const float* __restrict__ x,
                                                  float* __restrict__ out,
                                                  int b0)
{
    const int chunk = blockIdx.x;
    const int b     = b0 + blockIdx.y;
    const int tid   = threadIdx.x;
    const int c8    = tid & (NG - 1);
    const int pr    = tid >> 5;

    float g[8];
    {
        const float4 ga = __ldcg(&((const float4*)g_gate)[b * (C / 4) + c8 * 2]);
        const float4 gb = __ldcg(&((const float4*)g_gate)[b * (C / 4) + c8 * 2 + 1]);
        g[0] = ga.x; g[1] = ga.y; g[2] = ga.z; g[3] = ga.w;
        g[4] = gb.x; g[5] = gb.y; g[6] = gb.z; g[7] = gb.w;
    }

    const size_t off = ((size_t)(b * HW + chunk * MPPC + pr)) * C + c8 * 8;
    const float* xp = x + off;
    float*       op = out + off;

    uint32_t u0[8], u1[8], u2[8], u3[8];
    ld256_evict_first(xp,                  u0);
    ld256_evict_first(xp + (size_t) 8 * C, u1);
    ld256_evict_first(xp + (size_t)16 * C, u2);
    ld256_evict_first(xp + (size_t)24 * C, u3);

#pragma unroll
    for (int k = 0; k < 8; ++k) {
        u0[k] = __float_as_uint(__uint_as_float(u0[k]) * g[k]);
        u1[k] = __float_as_uint(__uint_as_float(u1[k]) * g[k]);
        u2[k] = __float_as_uint(__uint_as_float(u2[k]) * g[k]);
        u3[k] = __float_as_uint(__uint_as_float(u3[k]) * g[k]);
    }

    st256_evict_first(op,                  u0);
    st256_evict_first(op + (size_t) 8 * C, u1);
    st256_evict_first(op + (size_t)16 * C, u2);
    st256_evict_first(op + (size_t)24 * C, u3);
}

extern "C" void kernel_launch(void* const* d_in, const int* in_sizes, int n_in,
                              void* d_out, int out_size) {
    const float* x  = (const float*)d_in[0];
    const float* w1 = (const float*)d_in[1];
    const float* w2 = (const float*)d_in[2];
    float* out      = (float*)d_out;

    for (int g = 0; g < GROUPS; ++g) {
        const int b0 = g * BPG;
        dim3 ggrid(GCH, BPG);
        dim3 mgrid(MCH, BPG);
        gap_kernel<<<ggrid, 256>>>(x, b0);
        fc_kernel<<<BPG, 256>>>(w1, w2, b0);
        mul_kernel<<<mgrid, 256>>>(x, out, b0);
    }
}

// round 11
// speedup vs baseline: 1.2160x; 1.2160x over previous
#include <cuda_runtime.h>
#include <cstdint>

#define BATCH  32
#define HW     3136
#define C      256
#define C4     64            // C/4
#define CR     64
#define PPC    16            // pixels per chunk
#define CHUNKS 196           // HW / PPC
#define NG     32            // channel groups of 8 floats (C/8)

// Scratch (allocation-free per harness rules)
__device__ float g_partial[BATCH * CHUNKS * C];
__device__ float g_gate[BATCH * C];

// 256-bit load (default L2 policy)
__device__ __forceinline__ void ld256(const float* p, uint32_t* u) {
    asm volatile("ld.global.nc.v8.b32 {%0,%1,%2,%3,%4,%5,%6,%7}, [%8];"
                 : "=r"(u[0]), "=r"(u[1]), "=r"(u[2]), "=r"(u[3]),
                   "=r"(u[4]), "=r"(u[5]), "=r"(u[6]), "=r"(u[7])
                 : "l"(p));
}
// 256-bit store (default policy: allocate in L2, full-line writeback)
__device__ __forceinline__ void st256(float* p, const uint32_t* u) {
    asm volatile("st.global.v8.b32 [%0], {%1,%2,%3,%4,%5,%6,%7,%8};"
                 :: "l"(p),
                    "r"(u[0]), "r"(u[1]), "r"(u[2]), "r"(u[3]),
                    "r"(u[4]), "r"(u[5]), "r"(u[6]), "r"(u[7]));
}

// ---------------------------------------------------------------------------
// gap_kernel: R9's proven geometry (18.9us, 5.7TB/s). grid = (CHUNKS, BATCH)
// = 6272 blocks, 256 threads. c8 = tid&31, pr = tid>>5. 2 x v8 loads/thread,
// SMEM reduce across 8 pixel subgroups.
// ---------------------------------------------------------------------------
__global__ __launch_bounds__(256) void gap_kernel(const float* __restrict__ x)
{
    const int chunk = blockIdx.x;
    const int b     = blockIdx.y;
    const int tid   = threadIdx.x;
    const int c8    = tid & (NG - 1);
    const int pr    = tid >> 5;

    const float* xp = x + ((size_t)(b * HW + chunk * PPC + pr)) * C + c8 * 8;

    uint32_t u0[8], u1[8];
    ld256(xp,                 u0);
    ld256(xp + (size_t)8 * C, u1);

    __shared__ float red[8 * C];       // 8KB
    float* rp = &red[pr * C + c8 * 8];
#pragma unroll
    for (int k = 0; k < 8; ++k) {
        rp[k] = __uint_as_float(u0[k]) + __uint_as_float(u1[k]);
    }
    __syncthreads();

    float p0 = 0.0f;
#pragma unroll
    for (int g = 0; g < 8; ++g) {
        p0 += red[g * C + tid];
    }
    g_partial[(b * CHUNKS + chunk) * C + tid] = p0;
}

// ---------------------------------------------------------------------------
// fc_kernel: 32 blocks x 256 threads. 4-way accumulate over 196 partials,
// then squeeze->relu6->excite->hsigmoid -> gate.
// ---------------------------------------------------------------------------
__global__ __launch_bounds__(256) void fc_kernel(const float* __restrict__ w1,
                                                 const float* __restrict__ w2)
{
    const int b = blockIdx.x;
    const int t = threadIdx.x;

    __shared__ float s[C];
    __shared__ float h[CR];

    float s0 = 0.f, s1 = 0.f, s2 = 0.f, s3 = 0.f;
#pragma unroll
    for (int k = 0; k < CHUNKS; k += 4) {
        s0 += __ldcg(&g_partial[(b * CHUNKS + k + 0) * C + t]);
        s1 += __ldcg(&g_partial[(b * CHUNKS + k + 1) * C + t]);
        s2 += __ldcg(&g_partial[(b * CHUNKS + k + 2) * C + t]);
        s3 += __ldcg(&g_partial[(b * CHUNKS + k + 3) * C + t]);
    }
    s[t] = ((s0 + s1) + (s2 + s3)) * (1.0f / (float)HW);
    __syncthreads();

    if (t < CR) {
        float acc = 0.0f;
#pragma unroll 8
        for (int c = 0; c < C; ++c) {
            acc += s[c] * w1[c * CR + t];
        }
        h[t] = fminf(fmaxf(acc, 0.0f), 6.0f);
    }
    __syncthreads();

    float acc = 0.0f;
#pragma unroll
    for (int r = 0; r < CR; ++r) {
        acc += h[r] * w2[r * C + t];
    }
    g_gate[b * C + t] = fminf(fmaxf(acc + 3.0f, 0.0f), 6.0f) * (1.0f / 6.0f);
}

// ---------------------------------------------------------------------------
// mul_kernel: grid = (CHUNKS, BATCH) = 6272 blocks, 256 threads, lean.
// v8 loads (default policy) + PLAIN v8 stores — writes allocate in L2 and
// write back as full 128B dirty lines, instead of streaming sub-line bursts.
// ---------------------------------------------------------------------------
__global__ __launch_bounds__(256) void mul_kernel(const float* __restrict__ x,
                                                  float* __restrict__ out)
{
    const int chunk = blockIdx.x;
    const int b     = blockIdx.y;
    const int tid   = threadIdx.x;
    const int c8    = tid & (NG - 1);
    const int pr    = tid >> 5;

    float g[8];
    {
        const float4 ga = __ldcg(&((const float4*)g_gate)[b * (C / 4) + c8 * 2]);
        const float4 gb = __ldcg(&((const float4*)g_gate)[b * (C / 4) + c8 * 2 + 1]);
        g[0] = ga.x; g[1] = ga.y; g[2] = ga.z; g[3] = ga.w;
        g[4] = gb.x; g[5] = gb.y; g[6] = gb.z; g[7] = gb.w;
    }

    const size_t off = ((size_t)(b * HW + chunk * PPC + pr)) * C + c8 * 8;
    const float* xp = x + off;
    float*       op = out + off;

    uint32_t u0[8], u1[8];
    ld256(xp,                 u0);
    ld256(xp + (size_t)8 * C, u1);

#pragma unroll
    for (int k = 0; k < 8; ++k) {
        u0[k] = __float_as_uint(__uint_as_float(u0[k]) * g[k]);
        u1[k] = __float_as_uint(__uint_as_float(u1[k]) * g[k]);
    }

    st256(op,                 u0);
    st256(op + (size_t)8 * C, u1);
}

extern "C" void kernel_launch(void* const* d_in, const int* in_sizes, int n_in,
                              void* d_out, int out_size) {
    const float* x  = (const float*)d_in[0];
    const float* w1 = (const float*)d_in[1];
    const float* w2 = (const float*)d_in[2];
    float* out      = (float*)d_out;

    dim3 grid(CHUNKS, BATCH);
    gap_kernel<<<grid, 256>>>(x);
    fc_kernel<<<BATCH, 256>>>(w1, w2);
    mul_kernel<<<grid, 256>>>(x, out);
}